// round 1
// baseline (speedup 1.0000x reference)
#include <cuda_runtime.h>
#include <math.h>

#define SLEN 4096
#define NH 8
#define HD 64
#define BM 64
#define BN 64
#define NT 256
// shared layout strides
#define QK_STRIDE 68   // padded row stride for Qt/Kt/Ps
// out region sizes
#define OUT_ELEMS 2097152   // 4*1*1024*8*64
#define LSE_PER_RANK 8192   // 8*1024

__global__ __launch_bounds__(256) void zz_fa_kernel(
    const float* __restrict__ q,
    const float* __restrict__ k,
    const float* __restrict__ v,
    float* __restrict__ out)
{
    extern __shared__ float sm[];
    float* Qt = sm;                       // [HD][QK_STRIDE]   Q^T (d-major), pre-scaled
    float* Kt = Qt + HD * QK_STRIDE;      // [HD][QK_STRIDE]   K^T (d-major)
    float* Ps = Kt + HD * QK_STRIDE;      // [BM][QK_STRIDE]   P row-major (row=query)
    float* Vs = Ps + BM * QK_STRIDE;      // [BN][HD]          V natural layout

    const int qi = 63 - blockIdx.x;       // heavy tiles first
    const int h  = blockIdx.y;
    const int tid = threadIdx.x;
    const int tx = tid & 15;              // col group (d / key dim), 4 wide
    const int ty = tid >> 4;              // row group (query dim), 4 wide

    const int qbase = qi * BM;
    const float scale = 0.125f;           // 1/sqrt(64), exact power of two

    // ---- load Q tile (scaled) into Qt[d][row] ----
    for (int idx = tid; idx < BM * HD; idx += NT) {
        int row = idx >> 6, d = idx & 63;
        Qt[d * QK_STRIDE + row] = q[(qbase + row) * (NH * HD) + h * HD + d] * scale;
    }

    float o[4][4];
    float mrow[4], lrow[4];
#pragma unroll
    for (int i = 0; i < 4; i++) {
        mrow[i] = -INFINITY; lrow[i] = 0.f;
#pragma unroll
        for (int j = 0; j < 4; j++) o[i][j] = 0.f;
    }

    for (int jt = 0; jt <= qi; ++jt) {
        __syncthreads();   // protect Kt/Vs (prev GEMM1/GEMM2 readers done)
        const int kb = jt * BN;
        for (int idx = tid; idx < BN * HD; idx += NT) {
            int row = idx >> 6, d = idx & 63;
            int g = (kb + row) * (NH * HD) + h * HD + d;
            Kt[d * QK_STRIDE + row] = k[g];
            Vs[row * HD + d]        = v[g];
        }
        __syncthreads();

        // ---- GEMM1: S = Q K^T  (thread tile: rows ty*4.., cols tx*4..) ----
        float s[4][4];
#pragma unroll
        for (int i = 0; i < 4; i++)
#pragma unroll
            for (int j = 0; j < 4; j++) s[i][j] = 0.f;

#pragma unroll 4
        for (int kk = 0; kk < HD; kk += 4) {
            float4 qv[4], kv[4];
#pragma unroll
            for (int t = 0; t < 4; t++) {
                qv[t] = *reinterpret_cast<const float4*>(&Qt[(kk + t) * QK_STRIDE + ty * 4]);
                kv[t] = *reinterpret_cast<const float4*>(&Kt[(kk + t) * QK_STRIDE + tx * 4]);
            }
#pragma unroll
            for (int t = 0; t < 4; t++) {
                const float qa[4] = {qv[t].x, qv[t].y, qv[t].z, qv[t].w};
                const float ka[4] = {kv[t].x, kv[t].y, kv[t].z, kv[t].w};
#pragma unroll
                for (int i = 0; i < 4; i++)
#pragma unroll
                    for (int j = 0; j < 4; j++) s[i][j] += qa[i] * ka[j];
            }
        }

        // ---- causal mask on the diagonal tile ----
        if (jt == qi) {
#pragma unroll
            for (int i = 0; i < 4; i++) {
                int qrow = ty * 4 + i;
#pragma unroll
                for (int j = 0; j < 4; j++) {
                    int kcol = tx * 4 + j;
                    if (kcol > qrow) s[i][j] = -INFINITY;
                }
            }
        }

        // ---- online softmax (rows spread over the 16 tx threads) ----
#pragma unroll
        for (int i = 0; i < 4; i++) {
            float mx = fmaxf(fmaxf(s[i][0], s[i][1]), fmaxf(s[i][2], s[i][3]));
#pragma unroll
            for (int off = 8; off >= 1; off >>= 1)
                mx = fmaxf(mx, __shfl_xor_sync(0xffffffffu, mx, off));
            float mnew = fmaxf(mrow[i], mx);
            float alpha = __expf(mrow[i] - mnew);   // exp(-inf)=0 on first tile
            float rs = 0.f;
#pragma unroll
            for (int j = 0; j < 4; j++) {
                float p = __expf(s[i][j] - mnew);
                s[i][j] = p;
                rs += p;
            }
#pragma unroll
            for (int off = 8; off >= 1; off >>= 1)
                rs += __shfl_xor_sync(0xffffffffu, rs, off);
            lrow[i] = lrow[i] * alpha + rs;
            mrow[i] = mnew;
#pragma unroll
            for (int j = 0; j < 4; j++) o[i][j] *= alpha;
            // store P row-major with float4 (conflict-free)
            float4 pv = make_float4(s[i][0], s[i][1], s[i][2], s[i][3]);
            *reinterpret_cast<float4*>(&Ps[(ty * 4 + i) * QK_STRIDE + tx * 4]) = pv;
        }
        __syncthreads();

        // ---- GEMM2: O += P V ----
#pragma unroll 4
        for (int jl = 0; jl < BN; jl += 4) {
            float4 pv[4], vv[4];
#pragma unroll
            for (int i = 0; i < 4; i++)
                pv[i] = *reinterpret_cast<const float4*>(&Ps[(ty * 4 + i) * QK_STRIDE + jl]);
#pragma unroll
            for (int t = 0; t < 4; t++)
                vv[t] = *reinterpret_cast<const float4*>(&Vs[(jl + t) * HD + tx * 4]);
#pragma unroll
            for (int i = 0; i < 4; i++) {
                const float pa[4] = {pv[i].x, pv[i].y, pv[i].z, pv[i].w};
#pragma unroll
                for (int t = 0; t < 4; t++) {
                    const float va[4] = {vv[t].x, vv[t].y, vv[t].z, vv[t].w};
#pragma unroll
                    for (int j = 0; j < 4; j++) o[i][j] += pa[t] * va[j];
                }
            }
        }
    }

    // ---- epilogue: normalize, zigzag scatter of out and lse ----
#pragma unroll
    for (int i = 0; i < 4; i++) {
        int sg = qbase + ty * 4 + i;           // global query index
        int c = sg >> 9;                       // chunk of 512
        int r, sl;
        if (c < 4) { r = c;     sl = sg & 511; }
        else       { r = 7 - c; sl = 512 + (sg & 511); }
        float inv = 1.f / lrow[i];
        int base = r * 524288 + sl * 512 + h * 64 + tx * 4;
        float4 ov = make_float4(o[i][0] * inv, o[i][1] * inv, o[i][2] * inv, o[i][3] * inv);
        *reinterpret_cast<float4*>(&out[base]) = ov;
        if (tx == 0) {
            out[OUT_ELEMS + r * LSE_PER_RANK + h * 1024 + sl] = mrow[i] + logf(lrow[i]);
        }
    }
}

extern "C" void kernel_launch(void* const* d_in, const int* in_sizes, int n_in,
                              void* d_out, int out_size)
{
    const float* q = (const float*)d_in[0];
    const float* k = (const float*)d_in[1];
    const float* v = (const float*)d_in[2];
    float* out = (float*)d_out;

    const int smem_bytes = (3 * HD * QK_STRIDE + BN * HD) * (int)sizeof(float); // 68608
    cudaFuncSetAttribute(zz_fa_kernel, cudaFuncAttributeMaxDynamicSharedMemorySize, smem_bytes);

    dim3 grid(64, NH);
    zz_fa_kernel<<<grid, NT, smem_bytes>>>(q, k, v, out);
}